// round 9
// baseline (speedup 1.0000x reference)
#include <cuda_runtime.h>
#include <cuda_bf16.h>

// PositionalEncoding2D — final kernel (at the chip store wall).
//   pe[i,b,2p]   = sin(x[i,b,0] * dt[p])
//   pe[i,b,2p+1] = cos(x[i,b,1] * dt[p]),  dt[p] = exp(p * -ln(1e4)/256)
//
// Input : x  [65536 rows][2] fp32;  Output: [65536 rows][512] fp32 = 128 MB.
//
// Measured campaign summary (GB300, sm_103a):
//   R1  1 quad/thread  (MLP=1)          : 27.9 us kernel
//   R2  4 quads/thread (MLP=4)          : 20.7 us
//   R3  MLP=8 + __stcs                  : 30.0 us  (.cs store path is slow)
//   R6  MLP=8 plain STG.128             : 20.4 us  <- this kernel
//   R7  TMA bulk store (SMEM->GMEM)     : 21.5 us
//   R8  STG.256 (st.global.v8.f32)      : 20.4 us
// 134 MB / 20.4 us = 6.57 TB/s into L2 ~= 95% of the measured LTS crossbar
// cap (~6300 B/cyc @1095MHz = 6.9 TB/s), identical across STG.128 / STG.256 /
// TMA. Store-side LTS cap confirmed path-independent; this is the floor.
//
// Layout: one warp = 2 rows. Lane l owns quads {l, l+32, l+64, l+96} per row
// -> 8 independent coalesced STG.128 in flight. dt by recurrence from one
// __expf: pair step r = 1e4^(-1/256); +32-quad step multiplies by 0.1 exactly.

#define NUM_ROWS (2048 * 32)   // 65536

__global__ __launch_bounds__(256)
void pe2d_kernel(const float4* __restrict__ x, float4* __restrict__ out) {
    const int warp = (blockIdx.x * 256 + threadIdx.x) >> 5;  // row-pair index
    const int lane = threadIdx.x & 31;

    // Coords for rows 2w and 2w+1: 4 contiguous floats (uniform in warp)
    const float4 xy2 = __ldg(x + warp);
    // row0: (xy2.x, xy2.y)   row1: (xy2.z, xy2.w)

    // dt for quad t: exp(2t * C), C = -ln(1e4)/256
    const float twoC = -9.210340371976184f / 128.0f;
    const float r    = 0.9646616199111993f;            // pair step 1e4^(-1/256)
    const float d0 = __expf((float)lane * twoC);       // quad lane
    const float d1 = d0 * 0.1f;                        // quad lane+32
    const float d2 = d1 * 0.1f;
    const float d3 = d2 * 0.1f;
    const float e0 = d0 * r, e1 = d1 * r, e2 = d2 * r, e3 = d3 * r;

    float4* o = out + (size_t)warp * 256 + lane;

    float4 a;
    // row 0
    a.x = __sinf(xy2.x * d0); a.y = __cosf(xy2.y * d0);
    a.z = __sinf(xy2.x * e0); a.w = __cosf(xy2.y * e0);
    o[0] = a;
    a.x = __sinf(xy2.x * d1); a.y = __cosf(xy2.y * d1);
    a.z = __sinf(xy2.x * e1); a.w = __cosf(xy2.y * e1);
    o[32] = a;
    a.x = __sinf(xy2.x * d2); a.y = __cosf(xy2.y * d2);
    a.z = __sinf(xy2.x * e2); a.w = __cosf(xy2.y * e2);
    o[64] = a;
    a.x = __sinf(xy2.x * d3); a.y = __cosf(xy2.y * d3);
    a.z = __sinf(xy2.x * e3); a.w = __cosf(xy2.y * e3);
    o[96] = a;
    // row 1
    a.x = __sinf(xy2.z * d0); a.y = __cosf(xy2.w * d0);
    a.z = __sinf(xy2.z * e0); a.w = __cosf(xy2.w * e0);
    o[128] = a;
    a.x = __sinf(xy2.z * d1); a.y = __cosf(xy2.w * d1);
    a.z = __sinf(xy2.z * e1); a.w = __cosf(xy2.w * e1);
    o[160] = a;
    a.x = __sinf(xy2.z * d2); a.y = __cosf(xy2.w * d2);
    a.z = __sinf(xy2.z * e2); a.w = __cosf(xy2.w * e2);
    o[192] = a;
    a.x = __sinf(xy2.z * d3); a.y = __cosf(xy2.w * d3);
    a.z = __sinf(xy2.z * e3); a.w = __cosf(xy2.w * e3);
    o[224] = a;
}

extern "C" void kernel_launch(void* const* d_in, const int* in_sizes, int n_in,
                              void* d_out, int out_size) {
    const float4* x = (const float4*)d_in[0];
    float4* out = (float4*)d_out;
    // 65536 rows, 2 rows/warp, 8 warps/block -> 4096 blocks
    pe2d_kernel<<<NUM_ROWS / 16, 256>>>(x, out);
}

// round 12
// speedup vs baseline: 1.0102x; 1.0102x over previous
#include <cuda_runtime.h>
#include <cuda_bf16.h>

// PositionalEncoding2D — FINAL kernel, at the chip store wall.
//   pe[i,b,2p]   = sin(x[i,b,0] * dt[p])
//   pe[i,b,2p+1] = cos(x[i,b,1] * dt[p]),  dt[p] = exp(p * -ln(1e4)/256)
//
// Input : x  [65536 rows][2] fp32;  Output: [65536 rows][512] fp32 = 128 MB.
//
// Campaign summary (GB300, sm_103a; kernel-time per ncu):
//   R1  MLP=1  STG.128                  : 27.9 us
//   R2  MLP=4  STG.128                  : 20.7 us
//   R3  MLP=8  __stcs                   : 30.0 us  (.cs store path is slow)
//   R6  MLP=8  plain STG.128            : 20.4 us  <- this kernel
//   R7  TMA bulk store (SMEM->GMEM)     : 21.5 us
//   R8  STG.256 (st.global.v8.f32)      : 20.4 us
//   R9  rerun of R6                     : 21.4 us  (run-to-run noise ~5%)
// 134 MB / 20.4 us = 6.57 TB/s into L2 ~= 95% of the measured LTS crossbar
// cap (~6300 B/cyc @1095MHz ~= 6.9 TB/s), identical across STG.128/STG.256/
// TMA. Store cap is path-independent; output bytes are fixed by the problem;
// compute pipes are <25% busy. This is the floor for this problem.
//
// Layout: one warp = 2 rows. Lane l owns quads {l, l+32, l+64, l+96} per row
// -> 8 independent coalesced STG.128 in flight. dt by recurrence from one
// __expf: pair step r = 1e4^(-1/256); +32-quad step multiplies by 0.1 exactly.

#define NUM_ROWS (2048 * 32)   // 65536

__global__ __launch_bounds__(256)
void pe2d_kernel(const float4* __restrict__ x, float4* __restrict__ out) {
    const int warp = (blockIdx.x * 256 + threadIdx.x) >> 5;  // row-pair index
    const int lane = threadIdx.x & 31;

    // Coords for rows 2w and 2w+1: 4 contiguous floats (uniform in warp)
    const float4 xy2 = __ldg(x + warp);
    // row0: (xy2.x, xy2.y)   row1: (xy2.z, xy2.w)

    // dt for quad t: exp(2t * C), C = -ln(1e4)/256
    const float twoC = -9.210340371976184f / 128.0f;
    const float r    = 0.9646616199111993f;            // pair step 1e4^(-1/256)
    const float d0 = __expf((float)lane * twoC);       // quad lane
    const float d1 = d0 * 0.1f;                        // quad lane+32
    const float d2 = d1 * 0.1f;
    const float d3 = d2 * 0.1f;
    const float e0 = d0 * r, e1 = d1 * r, e2 = d2 * r, e3 = d3 * r;

    float4* o = out + (size_t)warp * 256 + lane;

    float4 a;
    // row 0
    a.x = __sinf(xy2.x * d0); a.y = __cosf(xy2.y * d0);
    a.z = __sinf(xy2.x * e0); a.w = __cosf(xy2.y * e0);
    o[0] = a;
    a.x = __sinf(xy2.x * d1); a.y = __cosf(xy2.y * d1);
    a.z = __sinf(xy2.x * e1); a.w = __cosf(xy2.y * e1);
    o[32] = a;
    a.x = __sinf(xy2.x * d2); a.y = __cosf(xy2.y * d2);
    a.z = __sinf(xy2.x * e2); a.w = __cosf(xy2.y * e2);
    o[64] = a;
    a.x = __sinf(xy2.x * d3); a.y = __cosf(xy2.y * d3);
    a.z = __sinf(xy2.x * e3); a.w = __cosf(xy2.y * e3);
    o[96] = a;
    // row 1
    a.x = __sinf(xy2.z * d0); a.y = __cosf(xy2.w * d0);
    a.z = __sinf(xy2.z * e0); a.w = __cosf(xy2.w * e0);
    o[128] = a;
    a.x = __sinf(xy2.z * d1); a.y = __cosf(xy2.w * d1);
    a.z = __sinf(xy2.z * e1); a.w = __cosf(xy2.w * e1);
    o[160] = a;
    a.x = __sinf(xy2.z * d2); a.y = __cosf(xy2.w * d2);
    a.z = __sinf(xy2.z * e2); a.w = __cosf(xy2.w * e2);
    o[192] = a;
    a.x = __sinf(xy2.z * d3); a.y = __cosf(xy2.w * d3);
    a.z = __sinf(xy2.z * e3); a.w = __cosf(xy2.w * e3);
    o[224] = a;
}

extern "C" void kernel_launch(void* const* d_in, const int* in_sizes, int n_in,
                              void* d_out, int out_size) {
    const float4* x = (const float4*)d_in[0];
    float4* out = (float4*)d_out;
    // 65536 rows, 2 rows/warp, 8 warps/block -> 4096 blocks
    pe2d_kernel<<<NUM_ROWS / 16, 256>>>(x, out);
}

// round 13
// speedup vs baseline: 1.0220x; 1.0116x over previous
#include <cuda_runtime.h>
#include <cuda_bf16.h>

// PositionalEncoding2D — FINAL kernel, at the chip store wall.
//   pe[i,b,2p]   = sin(x[i,b,0] * dt[p])
//   pe[i,b,2p+1] = cos(x[i,b,1] * dt[p]),  dt[p] = exp(p * -ln(1e4)/256)
//
// Input : x  [65536 rows][2] fp32;  Output: [65536 rows][512] fp32 = 128 MB.
//
// Campaign summary (GB300, sm_103a; kernel-time per ncu):
//   R1  MLP=1  STG.128                  : 27.9 us
//   R2  MLP=4  STG.128                  : 20.7 us
//   R3  MLP=8  __stcs                   : 30.0 us  (.cs store path is slow)
//   R6  MLP=8  plain STG.128            : 20.4 us  <- this kernel
//   R7  TMA bulk store (SMEM->GMEM)     : 21.5 us
//   R8  STG.256 (st.global.v8.f32)      : 20.4 us
//   R9/R12 reruns of R6                 : 21.4 / 20.4 us (noise band ~5%)
// 134 MB / 20.4 us = 6.57 TB/s into L2 ~= 95% of the measured LTS crossbar
// cap (~6300 B/cyc, path-independent: STG.128 = STG.256 = TMA). Output bytes
// are fixed by the problem; compute pipes <25% busy. This is the floor.
//
// Layout: one warp = 2 rows. Lane l owns quads {l, l+32, l+64, l+96} per row
// -> 8 independent coalesced STG.128 in flight. dt by recurrence from one
// __expf: pair step r = 1e4^(-1/256); +32-quad step multiplies by 0.1 exactly.

#define NUM_ROWS (2048 * 32)   // 65536

__global__ __launch_bounds__(256)
void pe2d_kernel(const float4* __restrict__ x, float4* __restrict__ out) {
    const int warp = (blockIdx.x * 256 + threadIdx.x) >> 5;  // row-pair index
    const int lane = threadIdx.x & 31;

    // Coords for rows 2w and 2w+1: 4 contiguous floats (uniform in warp)
    const float4 xy2 = __ldg(x + warp);
    // row0: (xy2.x, xy2.y)   row1: (xy2.z, xy2.w)

    // dt for quad t: exp(2t * C), C = -ln(1e4)/256
    const float twoC = -9.210340371976184f / 128.0f;
    const float r    = 0.9646616199111993f;            // pair step 1e4^(-1/256)
    const float d0 = __expf((float)lane * twoC);       // quad lane
    const float d1 = d0 * 0.1f;                        // quad lane+32
    const float d2 = d1 * 0.1f;
    const float d3 = d2 * 0.1f;
    const float e0 = d0 * r, e1 = d1 * r, e2 = d2 * r, e3 = d3 * r;

    float4* o = out + (size_t)warp * 256 + lane;

    float4 a;
    // row 0
    a.x = __sinf(xy2.x * d0); a.y = __cosf(xy2.y * d0);
    a.z = __sinf(xy2.x * e0); a.w = __cosf(xy2.y * e0);
    o[0] = a;
    a.x = __sinf(xy2.x * d1); a.y = __cosf(xy2.y * d1);
    a.z = __sinf(xy2.x * e1); a.w = __cosf(xy2.y * e1);
    o[32] = a;
    a.x = __sinf(xy2.x * d2); a.y = __cosf(xy2.y * d2);
    a.z = __sinf(xy2.x * e2); a.w = __cosf(xy2.y * e2);
    o[64] = a;
    a.x = __sinf(xy2.x * d3); a.y = __cosf(xy2.y * d3);
    a.z = __sinf(xy2.x * e3); a.w = __cosf(xy2.y * e3);
    o[96] = a;
    // row 1
    a.x = __sinf(xy2.z * d0); a.y = __cosf(xy2.w * d0);
    a.z = __sinf(xy2.z * e0); a.w = __cosf(xy2.w * e0);
    o[128] = a;
    a.x = __sinf(xy2.z * d1); a.y = __cosf(xy2.w * d1);
    a.z = __sinf(xy2.z * e1); a.w = __cosf(xy2.w * e1);
    o[160] = a;
    a.x = __sinf(xy2.z * d2); a.y = __cosf(xy2.w * d2);
    a.z = __sinf(xy2.z * e2); a.w = __cosf(xy2.w * e2);
    o[192] = a;
    a.x = __sinf(xy2.z * d3); a.y = __cosf(xy2.w * d3);
    a.z = __sinf(xy2.z * e3); a.w = __cosf(xy2.w * e3);
    o[224] = a;
}

extern "C" void kernel_launch(void* const* d_in, const int* in_sizes, int n_in,
                              void* d_out, int out_size) {
    const float4* x = (const float4*)d_in[0];
    float4* out = (float4*)d_out;
    // 65536 rows, 2 rows/warp, 8 warps/block -> 4096 blocks
    pe2d_kernel<<<NUM_ROWS / 16, 256>>>(x, out);
}